// round 5
// baseline (speedup 1.0000x reference)
#include <cuda_runtime.h>
#include <cstdint>
#include <math.h>

#define B 4096
#define D 256
#define NT 32
#define SMEM_BYTES 73728   // 2 x (A 128x36 + B 128x36) floats

// ---------------- persistent scratch (no allocations allowed) ----------------
__device__ int   g_bar_cnt;            // zero-init; self-resetting
__device__ volatile int g_bar_gen;
__device__ int   g_n0;
__device__ int   g_src[B];
__device__ __align__(16) float g_Ps[B * D];
__device__ float g_RP[NT * B];         // [col-tile q][row i]  (coalesced)
__device__ float g_L[B];
__device__ int   g_crossList[NT * NT];
__device__ int   g_ncross;
__device__ int   g_withinList[NT * NT];
__device__ int   g_nwithin;
__device__ float g_part2[NT * NT];     // dense by within-list slot
__device__ float g_part_focal[16];
__device__ float g_part_region[32 * 16];

// ---------------- helpers ----------------
__device__ __forceinline__ uint32_t smem_u32(const void* p) {
    uint32_t a;
    asm("{ .reg .u64 t; cvta.to.shared.u64 t, %1; cvt.u32.u64 %0, t; }" : "=r"(a) : "l"(p));
    return a;
}
__device__ __forceinline__ void cp16(uint32_t d, const void* s) {
    asm volatile("cp.async.cg.shared.global [%0], [%1], 16;" :: "r"(d), "l"(s));
}
__device__ __forceinline__ void cp_commit() { asm volatile("cp.async.commit_group;" ::: "memory"); }
__device__ __forceinline__ void cp_wait1()  { asm volatile("cp.async.wait_group 1;" ::: "memory"); }
__device__ __forceinline__ void cp_wait0()  { asm volatile("cp.async.wait_group 0;" ::: "memory"); }
__device__ __forceinline__ float round_tf32(float x) {
    float r;
    asm("cvt.rna.tf32.f32 %0, %1;" : "=f"(r) : "f"(x));
    return r;
}

// ---------------- global sense-reversing barrier (all CTAs resident) ----------------
__device__ __forceinline__ void gbar() {
    __syncthreads();
    if (threadIdx.x == 0) {
        __threadfence();
        int gen = g_bar_gen;
        if (atomicAdd(&g_bar_cnt, 1) == (int)gridDim.x - 1) {
            g_bar_cnt = 0;
            __threadfence();
            g_bar_gen = gen + 1;
        } else {
            while (g_bar_gen == gen) __nanosleep(64);
        }
        __threadfence();
    }
    __syncthreads();
}

// ---------------- 128x128x256 tf32 tile GEMM via mma.sync (validated R4) ----------------
// 8 warps 4(m) x 2(n); warp tile 32x64; per-warp 2x8 m16n8k8; acc[mt][nt][4].
// elem map (lane l, g=l>>2, tg=l&3): c0:(mt*16+g, nt*8+tg*2) c1:(+0,+1) c2:(+8,+0) c3:(+8,+1)
__device__ __forceinline__ void gemm_tile(char* sm, uint32_t sb, int row0, int col0,
                                          float (*acc)[8][4]) {
    int t = threadIdx.x;
    int w = t >> 5, l = t & 31;
    int wm = w & 3, wn = w >> 2;
    int g = l >> 2, tg = l & 3;
#pragma unroll
    for (int mt = 0; mt < 2; mt++)
#pragma unroll
        for (int nt = 0; nt < 8; nt++)
#pragma unroll
            for (int e = 0; e < 4; e++) acc[mt][nt][e] = 0.f;

#pragma unroll
    for (int u = 0; u < 4; u++) {       // prefetch chunk 0
        int idx = t + 256 * u, r = idx >> 3, q = idx & 7;
        uint32_t so = (uint32_t)(r * 36 + q * 4) * 4u;
        cp16(sb + so, &g_Ps[(row0 + r) * D + q * 4]);
        cp16(sb + 18432u + so, &g_Ps[(col0 + r) * D + q * 4]);
    }
    cp_commit();

    for (int c = 0; c < 8; c++) {
        uint32_t pb = (uint32_t)(c & 1) * 36864u;
        if (c < 7) {
            uint32_t nb = (uint32_t)((c + 1) & 1) * 36864u;
            int kk = (c + 1) * 32;
#pragma unroll
            for (int u = 0; u < 4; u++) {
                int idx = t + 256 * u, r = idx >> 3, q = idx & 7;
                uint32_t so = (uint32_t)(r * 36 + q * 4) * 4u;
                cp16(sb + nb + so, &g_Ps[(row0 + r) * D + kk + q * 4]);
                cp16(sb + nb + 18432u + so, &g_Ps[(col0 + r) * D + kk + q * 4]);
            }
            cp_commit();
            cp_wait1();
        } else {
            cp_wait0();
        }
        __syncthreads();
        const float* Asm = (const float*)(sm + pb);
        const float* Bsm = (const float*)(sm + pb + 18432);
#pragma unroll
        for (int ks = 0; ks < 4; ks++) {
            int k0 = ks * 8;
            uint32_t a[2][4], b[8][2];
#pragma unroll
            for (int mt = 0; mt < 2; mt++) {
                int ar = wm * 32 + mt * 16 + g;
                a[mt][0] = __float_as_uint(Asm[ar * 36 + k0 + tg]);
                a[mt][1] = __float_as_uint(Asm[(ar + 8) * 36 + k0 + tg]);
                a[mt][2] = __float_as_uint(Asm[ar * 36 + k0 + tg + 4]);
                a[mt][3] = __float_as_uint(Asm[(ar + 8) * 36 + k0 + tg + 4]);
            }
#pragma unroll
            for (int nt = 0; nt < 8; nt++) {
                int br = wn * 64 + nt * 8 + g;
                b[nt][0] = __float_as_uint(Bsm[br * 36 + k0 + tg]);
                b[nt][1] = __float_as_uint(Bsm[br * 36 + k0 + tg + 4]);
            }
#pragma unroll
            for (int mt = 0; mt < 2; mt++)
#pragma unroll
                for (int nt = 0; nt < 8; nt++)
                    asm volatile(
                        "mma.sync.aligned.m16n8k8.row.col.f32.tf32.tf32.f32 "
                        "{%0,%1,%2,%3}, {%4,%5,%6,%7}, {%8,%9}, {%0,%1,%2,%3};"
                        : "+f"(acc[mt][nt][0]), "+f"(acc[mt][nt][1]),
                          "+f"(acc[mt][nt][2]), "+f"(acc[mt][nt][3])
                        : "r"(a[mt][0]), "r"(a[mt][1]), "r"(a[mt][2]), "r"(a[mt][3]),
                          "r"(b[nt][0]), "r"(b[nt][1]));
        }
        __syncthreads();
    }
}

// ---------------- cross tile: row/col sums of exp(sim/T) over neg pairs ----------------
__device__ void cross_tile(char* sm, int by, int bx, int n0) {
    int row0 = by * 128, col0 = bx * 128;
    float acc[2][8][4];
    gemm_tile(sm, smem_u32(sm), row0, col0, acc);

    int t = threadIdx.x;
    int w = t >> 5, l = t & 31;
    int wm = w & 3, wn = w >> 2;
    int g = l >> 2, tg = l & 3;

    float rowp[2][2] = {{0.f,0.f},{0.f,0.f}};
    float colp[8][2];
#pragma unroll
    for (int nt = 0; nt < 8; nt++) { colp[nt][0] = 0.f; colp[nt][1] = 0.f; }
#pragma unroll
    for (int mt = 0; mt < 2; mt++) {
        int r0 = row0 + wm * 32 + mt * 16 + g;
        int r1 = r0 + 8;
        bool ga = (r0 < n0), gb = (r1 < n0);
#pragma unroll
        for (int nt = 0; nt < 8; nt++) {
            int c0 = col0 + wn * 64 + nt * 8 + tg * 2;
            bool ca = (c0 < n0), cb = (c0 + 1 < n0);
            float e00 = (ga != ca) ? expf(acc[mt][nt][0] * 10.0f) : 0.f;
            float e01 = (ga != cb) ? expf(acc[mt][nt][1] * 10.0f) : 0.f;
            float e10 = (gb != ca) ? expf(acc[mt][nt][2] * 10.0f) : 0.f;
            float e11 = (gb != cb) ? expf(acc[mt][nt][3] * 10.0f) : 0.f;
            rowp[mt][0] += e00 + e01;
            rowp[mt][1] += e10 + e11;
            colp[nt][0] += e00 + e10;
            colp[nt][1] += e01 + e11;
        }
    }
#pragma unroll
    for (int mt = 0; mt < 2; mt++)
#pragma unroll
        for (int h = 0; h < 2; h++) {
            rowp[mt][h] += __shfl_xor_sync(0xffffffffu, rowp[mt][h], 1);
            rowp[mt][h] += __shfl_xor_sync(0xffffffffu, rowp[mt][h], 2);
        }
#pragma unroll
    for (int nt = 0; nt < 8; nt++)
#pragma unroll
        for (int h = 0; h < 2; h++) {
            colp[nt][h] += __shfl_xor_sync(0xffffffffu, colp[nt][h], 4);
            colp[nt][h] += __shfl_xor_sync(0xffffffffu, colp[nt][h], 8);
            colp[nt][h] += __shfl_xor_sync(0xffffffffu, colp[nt][h], 16);
        }
    float* rowred = (float*)sm;            // [2][128]
    float* colred = (float*)(sm + 1024);   // [4][128]
    if (tg == 0) {
#pragma unroll
        for (int mt = 0; mt < 2; mt++) {
            rowred[wn * 128 + wm * 32 + mt * 16 + g]     = rowp[mt][0];
            rowred[wn * 128 + wm * 32 + mt * 16 + g + 8] = rowp[mt][1];
        }
    }
    if (l < 4) {
#pragma unroll
        for (int nt = 0; nt < 8; nt++)
#pragma unroll
            for (int h = 0; h < 2; h++)
                colred[wm * 128 + wn * 64 + nt * 8 + l * 2 + h] = colp[nt][h];
    }
    __syncthreads();
    if (t < 128) {
        float rs = rowred[t] + rowred[128 + t];
        float cs = colred[t] + colred[128 + t] + colred[256 + t] + colred[384 + t];
        int r = row0 + t, c = col0 + t;
        if (r < n0)  g_RP[bx * B + r] = rs;   // coalesced column-tile-major
        if (c >= n0) g_RP[by * B + c] = cs;
    }
    __syncthreads();
}

// ---------------- within tile: sum softplus(L - sim/T) over pos pairs ----------------
__device__ void within_tile(char* sm, int by, int bx, int n0, int slot) {
    int row0 = by * 128, col0 = bx * 128;
    float acc[2][8][4];
    gemm_tile(sm, smem_u32(sm), row0, col0, acc);

    int t = threadIdx.x;
    int w = t >> 5, l = t & 31;
    int wm = w & 3, wn = w >> 2;
    int g = l >> 2, tg = l & 3;
    bool offd = (bx > by);

    float Lr[2][2], Lc[8][2];
#pragma unroll
    for (int mt = 0; mt < 2; mt++) {
        int r0 = row0 + wm * 32 + mt * 16 + g;
        Lr[mt][0] = g_L[r0];
        Lr[mt][1] = g_L[r0 + 8];
    }
#pragma unroll
    for (int nt = 0; nt < 8; nt++) {
        int c0 = col0 + wn * 64 + nt * 8 + tg * 2;
        Lc[nt][0] = g_L[c0];
        Lc[nt][1] = g_L[c0 + 1];
    }
    float local = 0.f;
#pragma unroll
    for (int mt = 0; mt < 2; mt++) {
        int r0 = row0 + wm * 32 + mt * 16 + g;
#pragma unroll
        for (int nt = 0; nt < 8; nt++) {
            int c0 = col0 + wn * 64 + nt * 8 + tg * 2;
#pragma unroll
            for (int e = 0; e < 4; e++) {
                int r = r0 + (e >> 1) * 8;
                int c = c0 + (e & 1);
                if (((r < n0) == (c < n0)) && (r != c)) {
                    float s10 = acc[mt][nt][e] * 10.0f;
                    local += log1pf(expf(Lr[mt][e >> 1] - s10));
                    if (offd) local += log1pf(expf(Lc[nt][e & 1] - s10));
                }
            }
        }
    }
    float* red = (float*)sm;
    red[t] = local;
    __syncthreads();
    for (int off = 128; off > 0; off >>= 1) { if (t < off) red[t] += red[t + off]; __syncthreads(); }
    if (t == 0) g_part2[slot] = red[0];
    __syncthreads();
}

// ---------------- the single persistent kernel ----------------
__global__ void __launch_bounds__(256, 2) k_fused(
    const float* __restrict__ logits, const float* __restrict__ proj,
    const float* __restrict__ rp, const int* __restrict__ labels,
    float* __restrict__ out)
{
    extern __shared__ char sm[];
    const int grid = gridDim.x;
    const int cta = blockIdx.x;
    const int t = threadIdx.x;

    // ===== phase 0: CTA0 scan + tile lists; CTAs 1-16 focal; 17-48 region =====
    if (cta == 0) {
        int* sd = (int*)sm;
        int base = t * 16, cnt = 0, zm = 0;
#pragma unroll
        for (int u = 0; u < 16; u++) {
            int lz = (labels[base + u] == 0) ? 1 : 0;
            zm |= lz << u; cnt += lz;
        }
        sd[t] = cnt;
        __syncthreads();
        for (int off = 1; off < 256; off <<= 1) {
            int v = (t >= off) ? sd[t - off] : 0;
            __syncthreads();
            sd[t] += v;
            __syncthreads();
        }
        int n0 = sd[255];
        int zb = sd[t] - cnt;
#pragma unroll
        for (int u = 0; u < 16; u++) {
            int i = base + u, dest;
            if ((zm >> u) & 1) { dest = zb; zb++; }
            else               { dest = n0 + (i - zb); }
            g_src[dest] = i;
        }
        if (t == 0) g_n0 = n0;
        __syncthreads();
        // cross list: active iff row0 < n0 && col0+127 >= n0
        {
            int fl[4], c2 = 0;
#pragma unroll
            for (int u = 0; u < 4; u++) {
                int idx = t * 4 + u, by = idx >> 5, bx = idx & 31;
                fl[u] = (by * 128 < n0 && bx * 128 + 127 >= n0) ? 1 : 0;
                c2 += fl[u];
            }
            sd[t] = c2;
            __syncthreads();
            for (int off = 1; off < 256; off <<= 1) {
                int v = (t >= off) ? sd[t - off] : 0;
                __syncthreads();
                sd[t] += v;
                __syncthreads();
            }
            int pos = sd[t] - c2;
#pragma unroll
            for (int u = 0; u < 4; u++)
                if (fl[u]) g_crossList[pos++] = t * 4 + u;
            if (t == 255) g_ncross = sd[255];
            __syncthreads();
        }
        // within list: active iff bx>=by && !(row0+127 < n0 && col0 >= n0)
        {
            int fl[4], c2 = 0;
#pragma unroll
            for (int u = 0; u < 4; u++) {
                int idx = t * 4 + u, by = idx >> 5, bx = idx & 31;
                fl[u] = (bx >= by && !((by * 128 + 127 < n0) && (bx * 128 >= n0))) ? 1 : 0;
                c2 += fl[u];
            }
            sd[t] = c2;
            __syncthreads();
            for (int off = 1; off < 256; off <<= 1) {
                int v = (t >= off) ? sd[t - off] : 0;
                __syncthreads();
                sd[t] += v;
                __syncthreads();
            }
            int pos = sd[t] - c2;
#pragma unroll
            for (int u = 0; u < 4; u++)
                if (fl[u]) g_withinList[pos++] = t * 4 + u;
            if (t == 255) g_nwithin = sd[255];
            __syncthreads();
        }
    } else if (cta <= 16) {
        // focal: 256 elems per CTA
        float* red = (float*)sm;
        int i = (cta - 1) * 256 + t;
        float z0 = logits[2 * i] / 1.5f;
        float z1 = logits[2 * i + 1] / 1.5f;
        float m = fmaxf(z0, z1);
        float lse = m + logf(expf(z0 - m) + expf(z1 - m));
        float ce = lse - (labels[i] ? z1 : z0);
        float pt = expf(-ce);
        float om = 1.0f - pt;
        red[t] = om * om * ce;
        __syncthreads();
        for (int off = 128; off > 0; off >>= 1) { if (t < off) red[t] += red[t + off]; __syncthreads(); }
        if (t == 0) g_part_focal[cta - 1] = red[0];
    } else if (cta <= 48) {
        // region: 128 elems per CTA (threads 0-127 active)
        float (*red)[128] = (float (*)[128])sm;
        int rb = cta - 17;
        float accv[16];
#pragma unroll
        for (int k = 0; k < 16; k++) accv[k] = 0.f;
        if (t < 128) {
            int b = rb * 128 + t;
            int lab = labels[b];
            float p[4][2], lp[4][2], lpe[4][2], ent[4];
#pragma unroll
            for (int i = 0; i < 4; i++) {
                float x0 = rp[(i * B + b) * 2 + 0];
                float x1 = rp[(i * B + b) * 2 + 1];
                float m = fmaxf(x0, x1);
                float lse = m + logf(expf(x0 - m) + expf(x1 - m));
                lp[i][0] = x0 - lse; lp[i][1] = x1 - lse;
                p[i][0] = expf(lp[i][0]); p[i][1] = expf(lp[i][1]);
                lpe[i][0] = logf(p[i][0] + 1e-10f);
                lpe[i][1] = logf(p[i][1] + 1e-10f);
                ent[i] = p[i][0] * lp[i][0] + p[i][1] * lp[i][1];
                accv[12 + i] += -(lab ? lp[i][1] : lp[i][0]);
            }
            int pi = 0;
#pragma unroll
            for (int i = 0; i < 4; i++)
#pragma unroll
                for (int j = i + 1; j < 4; j++, pi++) {
                    float kl = ent[j] - (p[j][0] * lpe[i][0] + p[j][1] * lpe[i][1]);
                    if (lab) accv[pi] += kl; else accv[6 + pi] += kl;
                }
#pragma unroll
            for (int k = 0; k < 16; k++) red[k][t] = accv[k];
        }
        __syncthreads();
        for (int off = 64; off > 0; off >>= 1) {
            if (t < off) {
#pragma unroll
                for (int k = 0; k < 16; k++) red[k][t] += red[k][t + off];
            }
            __syncthreads();
        }
        if (t < 16) g_part_region[rb * 16 + t] = red[t][0];
    }
    gbar();

    // ===== phase 1: gather + L2-normalize + tf32-round =====
    {
        int gw = (cta * 256 + t) >> 5;
        int lane = t & 31;
        int nw = grid * 8;
        for (int row = gw; row < B; row += nw) {
            int src = g_src[row];
            const float* rrow = proj + src * D;
            float v[8]; float ss = 0.f;
#pragma unroll
            for (int u = 0; u < 8; u++) { v[u] = rrow[lane + u * 32]; ss += v[u] * v[u]; }
#pragma unroll
            for (int o = 16; o > 0; o >>= 1) ss += __shfl_xor_sync(0xffffffffu, ss, o);
            float inv = 1.0f / fmaxf(sqrtf(ss), 1e-12f);
            float* outp = g_Ps + row * D;
#pragma unroll
            for (int u = 0; u < 8; u++) outp[lane + u * 32] = round_tf32(v[u] * inv);
        }
    }
    gbar();

    // ===== phase 2: cross tiles =====
    int n0 = g_n0;
    {
        int nc = g_ncross;
        for (int ti = cta; ti < nc; ti += grid) {
            int tile = g_crossList[ti];
            cross_tile(sm, tile >> 5, tile & 31, n0);
        }
    }
    gbar();

    // ===== phase 3: L[i] = log(sum of partials), coalesced =====
    {
        int i = cta * 256 + t;
        if (i < B) {
            int lo, hi;
            if (i < n0) { lo = n0 >> 7; hi = NT - 1; }
            else        { lo = 0; hi = (n0 - 1) >> 7; }
            float s = 0.f;
            for (int q = lo; q <= hi; q++) s += g_RP[q * B + i];
            g_L[i] = logf(s);
        }
    }
    gbar();

    // ===== phase 4: within tiles =====
    {
        int nwv = g_nwithin;
        for (int ti = cta; ti < nwv; ti += grid) {
            int tile = g_withinList[ti];
            within_tile(sm, tile >> 5, tile & 31, n0, ti);
        }
    }
    gbar();

    // ===== phase 5: final combine (CTA 0) =====
    if (cta == 0) {
        float* red = (float*)sm;
        float* sreg = (float*)(sm + 1024);
        float* sfoc = (float*)(sm + 1024 + 64);
        int nwv = g_nwithin;
        float s = 0.f;
        for (int i = t; i < nwv; i += 256) s += g_part2[i];
        red[t] = s;
        __syncthreads();
        for (int off = 128; off > 0; off >>= 1) { if (t < off) red[t] += red[t + off]; __syncthreads(); }
        if (t < 16) {
            float a = 0.f;
            for (int blk = 0; blk < 32; blk++) a += g_part_region[blk * 16 + t];
            sreg[t] = a;
        }
        if (t == 16) {
            float f = 0.f;
            for (int i = 0; i < 16; i++) f += g_part_focal[i];
            sfoc[0] = f;
        }
        __syncthreads();
        if (t == 0) {
            float cont = red[0] / (float)B;
            float foc = sfoc[0] / (float)B;
            float pd = (float)(B - n0), ct = (float)n0;
            float rl = 0.f;
            for (int pi = 0; pi < 6; pi++) {
                float kpd = (pd > 0.f) ? sreg[pi]     / fmaxf(pd, 1.f) : 0.f;
                float kct = (ct > 0.f) ? sreg[6 + pi] / fmaxf(ct, 1.f) : 0.f;
                rl += kpd + kct;
            }
            for (int i = 0; i < 4; i++) rl += sreg[12 + i] / (float)B;
            rl /= 10.0f;                 // R*(R-1)/2 + R = 6 + 4
            out[0] = foc + 0.5f * cont + 0.3f * rl;
        }
    }
}

// ---------------- launch ----------------
extern "C" void kernel_launch(void* const* d_in, const int* in_sizes, int n_in,
                              void* d_out, int out_size) {
    const float* logits = nullptr;
    const float* proj   = nullptr;
    const float* rp     = nullptr;
    const int*   labels = nullptr;
    for (int i = 0; i < n_in; i++) {
        switch (in_sizes[i]) {
            case B * 2:        logits = (const float*)d_in[i]; break;
            case B * D:        proj   = (const float*)d_in[i]; break;
            case 4 * B * 2:    rp     = (const float*)d_in[i]; break;
            case B:            labels = (const int*)d_in[i];   break;
        }
    }
    int nsm = 0;
    cudaDeviceGetAttribute(&nsm, cudaDevAttrMultiProcessorCount, 0);
    int grid = 2 * nsm;   // all CTAs resident (launch_bounds(256,2), 72KB smem x2 <= 228KB)
    cudaFuncSetAttribute(k_fused, cudaFuncAttributeMaxDynamicSharedMemorySize, SMEM_BYTES);
    k_fused<<<grid, 256, SMEM_BYTES>>>(logits, proj, rp, labels, (float*)d_out);
}

// round 6
// speedup vs baseline: 1.0268x; 1.0268x over previous
#include <cuda_runtime.h>
#include <cstdint>
#include <math.h>

#define B 4096
#define D 256
#define NT 32
#define SMEM_BYTES 73728   // 2 x (A 128x36 + B 128x36) floats

// ---------------- persistent scratch (no allocations allowed) ----------------
__device__ int   g_bar_cnt;            // zero-init; self-resetting
__device__ volatile int g_bar_gen;
__device__ int   g_n0;
__device__ int   g_src[B];
__device__ __align__(16) float g_Ps[B * D];
__device__ float g_RP[NT * B];         // [col-tile q][row i]  (coalesced)
__device__ float g_L[B];
__device__ int   g_crossList[NT * NT];
__device__ int   g_ncross;
__device__ int   g_withinList[NT * NT];
__device__ int   g_nwithin;
__device__ float g_part2[NT * NT];     // dense by within-list slot
__device__ float g_part_focal[16];
__device__ float g_part_region[32 * 16];

// ---------------- helpers ----------------
__device__ __forceinline__ uint32_t smem_u32(const void* p) {
    uint32_t a;
    asm("{ .reg .u64 t; cvta.to.shared.u64 t, %1; cvt.u32.u64 %0, t; }" : "=r"(a) : "l"(p));
    return a;
}
__device__ __forceinline__ void cp16(uint32_t d, const void* s) {
    asm volatile("cp.async.cg.shared.global [%0], [%1], 16;" :: "r"(d), "l"(s));
}
__device__ __forceinline__ void cp_commit() { asm volatile("cp.async.commit_group;" ::: "memory"); }
__device__ __forceinline__ void cp_wait1()  { asm volatile("cp.async.wait_group 1;" ::: "memory"); }
__device__ __forceinline__ void cp_wait0()  { asm volatile("cp.async.wait_group 0;" ::: "memory"); }
__device__ __forceinline__ float round_tf32(float x) {
    float r;
    asm("cvt.rna.tf32.f32 %0, %1;" : "=f"(r) : "f"(x));
    return r;
}
// fast softplus: log(1+e^x). Typical x here is ~7.7 +- 0.6, |x|<2.1 is a ~14-sigma event.
__device__ __forceinline__ float softplus_f(float x) {
    float ax = fabsf(x);
    float m  = fmaxf(x, 0.0f);
    float y  = __expf(-ax);                 // MUFU.EX2 path, rel err ~2^-21
    if (ax < 2.1f) return m + log1pf(y);    // precise fallback (cold)
    float y2 = y * y;                       // log1p poly, |err| <= y^5/5 ~ 5.5e-6
    return m + (y - 0.5f * y2 + 0.33333333f * y2 * y - 0.25f * y2 * y2);
}

// ---------------- global sense-reversing barrier (all CTAs resident) ----------------
__device__ __forceinline__ void gbar() {
    __syncthreads();
    if (threadIdx.x == 0) {
        __threadfence();
        int gen = g_bar_gen;
        if (atomicAdd(&g_bar_cnt, 1) == (int)gridDim.x - 1) {
            g_bar_cnt = 0;
            __threadfence();
            g_bar_gen = gen + 1;
        } else {
            while (g_bar_gen == gen) __nanosleep(64);
        }
        __threadfence();
    }
    __syncthreads();
}

// ---------------- 128x128x256 tf32 tile GEMM via mma.sync (validated R4/R5) ----------------
// 8 warps 4(m) x 2(n); warp tile 32x64; per-warp 2x8 m16n8k8; acc[mt][nt][4].
// elem map (lane l, g=l>>2, tg=l&3): c0:(mt*16+g, nt*8+tg*2) c1:(+0,+1) c2:(+8,+0) c3:(+8,+1)
__device__ __forceinline__ void gemm_tile(char* sm, uint32_t sb, int row0, int col0,
                                          float (*acc)[8][4]) {
    int t = threadIdx.x;
    int w = t >> 5, l = t & 31;
    int wm = w & 3, wn = w >> 2;
    int g = l >> 2, tg = l & 3;
#pragma unroll
    for (int mt = 0; mt < 2; mt++)
#pragma unroll
        for (int nt = 0; nt < 8; nt++)
#pragma unroll
            for (int e = 0; e < 4; e++) acc[mt][nt][e] = 0.f;

#pragma unroll
    for (int u = 0; u < 4; u++) {       // prefetch chunk 0
        int idx = t + 256 * u, r = idx >> 3, q = idx & 7;
        uint32_t so = (uint32_t)(r * 36 + q * 4) * 4u;
        cp16(sb + so, &g_Ps[(row0 + r) * D + q * 4]);
        cp16(sb + 18432u + so, &g_Ps[(col0 + r) * D + q * 4]);
    }
    cp_commit();

    for (int c = 0; c < 8; c++) {
        uint32_t pb = (uint32_t)(c & 1) * 36864u;
        if (c < 7) {
            uint32_t nb = (uint32_t)((c + 1) & 1) * 36864u;
            int kk = (c + 1) * 32;
#pragma unroll
            for (int u = 0; u < 4; u++) {
                int idx = t + 256 * u, r = idx >> 3, q = idx & 7;
                uint32_t so = (uint32_t)(r * 36 + q * 4) * 4u;
                cp16(sb + nb + so, &g_Ps[(row0 + r) * D + kk + q * 4]);
                cp16(sb + nb + 18432u + so, &g_Ps[(col0 + r) * D + kk + q * 4]);
            }
            cp_commit();
            cp_wait1();
        } else {
            cp_wait0();
        }
        __syncthreads();
        const float* Asm = (const float*)(sm + pb);
        const float* Bsm = (const float*)(sm + pb + 18432);
#pragma unroll
        for (int ks = 0; ks < 4; ks++) {
            int k0 = ks * 8;
            uint32_t a[2][4], b[8][2];
#pragma unroll
            for (int mt = 0; mt < 2; mt++) {
                int ar = wm * 32 + mt * 16 + g;
                a[mt][0] = __float_as_uint(Asm[ar * 36 + k0 + tg]);
                a[mt][1] = __float_as_uint(Asm[(ar + 8) * 36 + k0 + tg]);
                a[mt][2] = __float_as_uint(Asm[ar * 36 + k0 + tg + 4]);
                a[mt][3] = __float_as_uint(Asm[(ar + 8) * 36 + k0 + tg + 4]);
            }
#pragma unroll
            for (int nt = 0; nt < 8; nt++) {
                int br = wn * 64 + nt * 8 + g;
                b[nt][0] = __float_as_uint(Bsm[br * 36 + k0 + tg]);
                b[nt][1] = __float_as_uint(Bsm[br * 36 + k0 + tg + 4]);
            }
#pragma unroll
            for (int mt = 0; mt < 2; mt++)
#pragma unroll
                for (int nt = 0; nt < 8; nt++)
                    asm volatile(
                        "mma.sync.aligned.m16n8k8.row.col.f32.tf32.tf32.f32 "
                        "{%0,%1,%2,%3}, {%4,%5,%6,%7}, {%8,%9}, {%0,%1,%2,%3};"
                        : "+f"(acc[mt][nt][0]), "+f"(acc[mt][nt][1]),
                          "+f"(acc[mt][nt][2]), "+f"(acc[mt][nt][3])
                        : "r"(a[mt][0]), "r"(a[mt][1]), "r"(a[mt][2]), "r"(a[mt][3]),
                          "r"(b[nt][0]), "r"(b[nt][1]));
        }
        __syncthreads();
    }
}

// ---------------- cross tile: row/col sums of exp(sim/T) over neg pairs ----------------
__device__ void cross_tile(char* sm, int by, int bx, int n0) {
    int row0 = by * 128, col0 = bx * 128;
    float acc[2][8][4];
    gemm_tile(sm, smem_u32(sm), row0, col0, acc);

    int t = threadIdx.x;
    int w = t >> 5, l = t & 31;
    int wm = w & 3, wn = w >> 2;
    int g = l >> 2, tg = l & 3;

    float rowp[2][2] = {{0.f,0.f},{0.f,0.f}};
    float colp[8][2];
#pragma unroll
    for (int nt = 0; nt < 8; nt++) { colp[nt][0] = 0.f; colp[nt][1] = 0.f; }
#pragma unroll
    for (int mt = 0; mt < 2; mt++) {
        int r0 = row0 + wm * 32 + mt * 16 + g;
        int r1 = r0 + 8;
        bool ga = (r0 < n0), gb = (r1 < n0);
#pragma unroll
        for (int nt = 0; nt < 8; nt++) {
            int c0 = col0 + wn * 64 + nt * 8 + tg * 2;
            bool ca = (c0 < n0), cb = (c0 + 1 < n0);
            float e00 = (ga != ca) ? __expf(acc[mt][nt][0] * 10.0f) : 0.f;
            float e01 = (ga != cb) ? __expf(acc[mt][nt][1] * 10.0f) : 0.f;
            float e10 = (gb != ca) ? __expf(acc[mt][nt][2] * 10.0f) : 0.f;
            float e11 = (gb != cb) ? __expf(acc[mt][nt][3] * 10.0f) : 0.f;
            rowp[mt][0] += e00 + e01;
            rowp[mt][1] += e10 + e11;
            colp[nt][0] += e00 + e10;
            colp[nt][1] += e01 + e11;
        }
    }
#pragma unroll
    for (int mt = 0; mt < 2; mt++)
#pragma unroll
        for (int h = 0; h < 2; h++) {
            rowp[mt][h] += __shfl_xor_sync(0xffffffffu, rowp[mt][h], 1);
            rowp[mt][h] += __shfl_xor_sync(0xffffffffu, rowp[mt][h], 2);
        }
#pragma unroll
    for (int nt = 0; nt < 8; nt++)
#pragma unroll
        for (int h = 0; h < 2; h++) {
            colp[nt][h] += __shfl_xor_sync(0xffffffffu, colp[nt][h], 4);
            colp[nt][h] += __shfl_xor_sync(0xffffffffu, colp[nt][h], 8);
            colp[nt][h] += __shfl_xor_sync(0xffffffffu, colp[nt][h], 16);
        }
    float* rowred = (float*)sm;            // [2][128]
    float* colred = (float*)(sm + 1024);   // [4][128]
    if (tg == 0) {
#pragma unroll
        for (int mt = 0; mt < 2; mt++) {
            rowred[wn * 128 + wm * 32 + mt * 16 + g]     = rowp[mt][0];
            rowred[wn * 128 + wm * 32 + mt * 16 + g + 8] = rowp[mt][1];
        }
    }
    if (l < 4) {
#pragma unroll
        for (int nt = 0; nt < 8; nt++)
#pragma unroll
            for (int h = 0; h < 2; h++)
                colred[wm * 128 + wn * 64 + nt * 8 + l * 2 + h] = colp[nt][h];
    }
    __syncthreads();
    if (t < 128) {
        float rs = rowred[t] + rowred[128 + t];
        float cs = colred[t] + colred[128 + t] + colred[256 + t] + colred[384 + t];
        int r = row0 + t, c = col0 + t;
        if (r < n0)  g_RP[bx * B + r] = rs;   // coalesced column-tile-major
        if (c >= n0) g_RP[by * B + c] = cs;
    }
    __syncthreads();
}

// ---------------- within epilogue: sum softplus(L - sim/T) over pos pairs ----------------
__device__ void within_epilogue(char* sm, int by, int bx, int n0, int slot,
                                float (*acc)[8][4]) {
    int row0 = by * 128, col0 = bx * 128;
    int t = threadIdx.x;
    int w = t >> 5, l = t & 31;
    int wm = w & 3, wn = w >> 2;
    int g = l >> 2, tg = l & 3;
    bool offd = (bx > by);

    float Lr[2][2], Lc[8][2];
#pragma unroll
    for (int mt = 0; mt < 2; mt++) {
        int r0 = row0 + wm * 32 + mt * 16 + g;
        Lr[mt][0] = g_L[r0];
        Lr[mt][1] = g_L[r0 + 8];
    }
#pragma unroll
    for (int nt = 0; nt < 8; nt++) {
        int c0 = col0 + wn * 64 + nt * 8 + tg * 2;
        Lc[nt][0] = g_L[c0];
        Lc[nt][1] = g_L[c0 + 1];
    }
    float local = 0.f;
#pragma unroll
    for (int mt = 0; mt < 2; mt++) {
        int r0 = row0 + wm * 32 + mt * 16 + g;
#pragma unroll
        for (int nt = 0; nt < 8; nt++) {
            int c0 = col0 + wn * 64 + nt * 8 + tg * 2;
#pragma unroll
            for (int e = 0; e < 4; e++) {
                int r = r0 + (e >> 1) * 8;
                int c = c0 + (e & 1);
                if (((r < n0) == (c < n0)) && (r != c)) {
                    float s10 = acc[mt][nt][e] * 10.0f;
                    local += softplus_f(Lr[mt][e >> 1] - s10);
                    if (offd) local += softplus_f(Lc[nt][e & 1] - s10);
                }
            }
        }
    }
    float* red = (float*)sm;
    red[t] = local;
    __syncthreads();
    for (int off = 128; off > 0; off >>= 1) { if (t < off) red[t] += red[t + off]; __syncthreads(); }
    if (t == 0) g_part2[slot] = red[0];
    __syncthreads();
}

// ---------------- the single persistent kernel ----------------
__global__ void __launch_bounds__(256, 2) k_fused(
    const float* __restrict__ logits, const float* __restrict__ proj,
    const float* __restrict__ rp, const int* __restrict__ labels,
    float* __restrict__ out)
{
    extern __shared__ char sm[];
    const int grid = gridDim.x;
    const int cta = blockIdx.x;
    const int t = threadIdx.x;

    // ===== phase 0: CTA0 scan + tile lists; CTAs 1-16 focal; 17-48 region =====
    if (cta == 0) {
        int* sd = (int*)sm;
        int base = t * 16, cnt = 0, zm = 0;
#pragma unroll
        for (int u = 0; u < 16; u++) {
            int lz = (labels[base + u] == 0) ? 1 : 0;
            zm |= lz << u; cnt += lz;
        }
        sd[t] = cnt;
        __syncthreads();
        for (int off = 1; off < 256; off <<= 1) {
            int v = (t >= off) ? sd[t - off] : 0;
            __syncthreads();
            sd[t] += v;
            __syncthreads();
        }
        int n0 = sd[255];
        int zb = sd[t] - cnt;
#pragma unroll
        for (int u = 0; u < 16; u++) {
            int i = base + u, dest;
            if ((zm >> u) & 1) { dest = zb; zb++; }
            else               { dest = n0 + (i - zb); }
            g_src[dest] = i;
        }
        if (t == 0) g_n0 = n0;
        __syncthreads();
        // cross list: active iff row0 < n0 && col0+127 >= n0
        {
            int fl[4], c2 = 0;
#pragma unroll
            for (int u = 0; u < 4; u++) {
                int idx = t * 4 + u, by = idx >> 5, bx = idx & 31;
                fl[u] = (by * 128 < n0 && bx * 128 + 127 >= n0) ? 1 : 0;
                c2 += fl[u];
            }
            sd[t] = c2;
            __syncthreads();
            for (int off = 1; off < 256; off <<= 1) {
                int v = (t >= off) ? sd[t - off] : 0;
                __syncthreads();
                sd[t] += v;
                __syncthreads();
            }
            int pos = sd[t] - c2;
#pragma unroll
            for (int u = 0; u < 4; u++)
                if (fl[u]) g_crossList[pos++] = t * 4 + u;
            if (t == 255) g_ncross = sd[255];
            __syncthreads();
        }
        // within list: active iff bx>=by && !(row0+127 < n0 && col0 >= n0)
        {
            int fl[4], c2 = 0;
#pragma unroll
            for (int u = 0; u < 4; u++) {
                int idx = t * 4 + u, by = idx >> 5, bx = idx & 31;
                fl[u] = (bx >= by && !((by * 128 + 127 < n0) && (bx * 128 >= n0))) ? 1 : 0;
                c2 += fl[u];
            }
            sd[t] = c2;
            __syncthreads();
            for (int off = 1; off < 256; off <<= 1) {
                int v = (t >= off) ? sd[t - off] : 0;
                __syncthreads();
                sd[t] += v;
                __syncthreads();
            }
            int pos = sd[t] - c2;
#pragma unroll
            for (int u = 0; u < 4; u++)
                if (fl[u]) g_withinList[pos++] = t * 4 + u;
            if (t == 255) g_nwithin = sd[255];
            __syncthreads();
        }
    } else if (cta <= 16) {
        // focal: 256 elems per CTA
        float* red = (float*)sm;
        int i = (cta - 1) * 256 + t;
        float z0 = logits[2 * i] / 1.5f;
        float z1 = logits[2 * i + 1] / 1.5f;
        float m = fmaxf(z0, z1);
        float lse = m + logf(expf(z0 - m) + expf(z1 - m));
        float ce = lse - (labels[i] ? z1 : z0);
        float pt = expf(-ce);
        float om = 1.0f - pt;
        red[t] = om * om * ce;
        __syncthreads();
        for (int off = 128; off > 0; off >>= 1) { if (t < off) red[t] += red[t + off]; __syncthreads(); }
        if (t == 0) g_part_focal[cta - 1] = red[0];
    } else if (cta <= 48) {
        // region: 128 elems per CTA (threads 0-127 active)
        float (*red)[128] = (float (*)[128])sm;
        int rb = cta - 17;
        float accv[16];
#pragma unroll
        for (int k = 0; k < 16; k++) accv[k] = 0.f;
        if (t < 128) {
            int b = rb * 128 + t;
            int lab = labels[b];
            float p[4][2], lp[4][2], lpe[4][2], ent[4];
#pragma unroll
            for (int i = 0; i < 4; i++) {
                float x0 = rp[(i * B + b) * 2 + 0];
                float x1 = rp[(i * B + b) * 2 + 1];
                float m = fmaxf(x0, x1);
                float lse = m + logf(expf(x0 - m) + expf(x1 - m));
                lp[i][0] = x0 - lse; lp[i][1] = x1 - lse;
                p[i][0] = expf(lp[i][0]); p[i][1] = expf(lp[i][1]);
                lpe[i][0] = logf(p[i][0] + 1e-10f);
                lpe[i][1] = logf(p[i][1] + 1e-10f);
                ent[i] = p[i][0] * lp[i][0] + p[i][1] * lp[i][1];
                accv[12 + i] += -(lab ? lp[i][1] : lp[i][0]);
            }
            int pi = 0;
#pragma unroll
            for (int i = 0; i < 4; i++)
#pragma unroll
                for (int j = i + 1; j < 4; j++, pi++) {
                    float kl = ent[j] - (p[j][0] * lpe[i][0] + p[j][1] * lpe[i][1]);
                    if (lab) accv[pi] += kl; else accv[6 + pi] += kl;
                }
#pragma unroll
            for (int k = 0; k < 16; k++) red[k][t] = accv[k];
        }
        __syncthreads();
        for (int off = 64; off > 0; off >>= 1) {
            if (t < off) {
#pragma unroll
                for (int k = 0; k < 16; k++) red[k][t] += red[k][t + off];
            }
            __syncthreads();
        }
        if (t < 16) g_part_region[rb * 16 + t] = red[t][0];
    }
    gbar();

    // ===== phase 1: gather + L2-normalize + tf32-round =====
    {
        int gw = (cta * 256 + t) >> 5;
        int lane = t & 31;
        int nw = grid * 8;
        for (int row = gw; row < B; row += nw) {
            int src = g_src[row];
            const float* rrow = proj + src * D;
            float v[8]; float ss = 0.f;
#pragma unroll
            for (int u = 0; u < 8; u++) { v[u] = rrow[lane + u * 32]; ss += v[u] * v[u]; }
#pragma unroll
            for (int o = 16; o > 0; o >>= 1) ss += __shfl_xor_sync(0xffffffffu, ss, o);
            float inv = 1.0f / fmaxf(sqrtf(ss), 1e-12f);
            float* outp = g_Ps + row * D;
#pragma unroll
            for (int u = 0; u < 8; u++) outp[lane + u * 32] = round_tf32(v[u] * inv);
        }
    }
    gbar();

    // ===== phase 2: ALL tile GEMMs (cross full; within GEMM held in regs) =====
    int n0 = g_n0;
    float accW[2][8][4];
    int heldSlot = -1, heldTile = 0;
    int nDefer = 0;
    int deferList[4];
    {
        int nc = g_ncross, nwv = g_nwithin, tot = nc + nwv;
        for (int wk = cta; wk < tot; wk += grid) {
            if (wk < nc) {
                int tile = g_crossList[wk];
                cross_tile(sm, tile >> 5, tile & 31, n0);
            } else {
                int slot = wk - nc;
                if (heldSlot < 0) {
                    heldSlot = slot;
                    heldTile = g_withinList[slot];
                    gemm_tile(sm, smem_u32(sm), (heldTile >> 5) * 128,
                              (heldTile & 31) * 128, accW);
                } else if (nDefer < 4) {
                    deferList[nDefer++] = slot;   // rare overflow: recompute after L
                }
            }
        }
    }
    gbar();

    // ===== phase 3: L[i] = log(sum of partials), coalesced =====
    {
        int i = cta * 256 + t;
        if (i < B) {
            int lo, hi;
            if (i < n0) { lo = n0 >> 7; hi = NT - 1; }
            else        { lo = 0; hi = (n0 - 1) >> 7; }
            float s = 0.f;
            for (int q = lo; q <= hi; q++) s += g_RP[q * B + i];
            g_L[i] = logf(s);
        }
    }
    gbar();

    // ===== phase 4: within epilogues (held acc) + deferred recompute =====
    if (heldSlot >= 0)
        within_epilogue(sm, heldTile >> 5, heldTile & 31, n0, heldSlot, accW);
    for (int d2 = 0; d2 < nDefer; d2++) {
        int slot = deferList[d2];
        int tile = g_withinList[slot];
        float accD[2][8][4];
        gemm_tile(sm, smem_u32(sm), (tile >> 5) * 128, (tile & 31) * 128, accD);
        within_epilogue(sm, tile >> 5, tile & 31, n0, slot, accD);
    }
    gbar();

    // ===== phase 5: final combine (CTA 0) =====
    if (cta == 0) {
        float* red = (float*)sm;
        float* sreg = (float*)(sm + 1024);
        float* sfoc = (float*)(sm + 1024 + 64);
        int nwv = g_nwithin;
        float s = 0.f;
        for (int i = t; i < nwv; i += 256) s += g_part2[i];
        red[t] = s;
        __syncthreads();
        for (int off = 128; off > 0; off >>= 1) { if (t < off) red[t] += red[t + off]; __syncthreads(); }
        if (t < 16) {
            float a = 0.f;
            for (int blk = 0; blk < 32; blk++) a += g_part_region[blk * 16 + t];
            sreg[t] = a;
        }
        if (t == 16) {
            float f = 0.f;
            for (int i = 0; i < 16; i++) f += g_part_focal[i];
            sfoc[0] = f;
        }
        __syncthreads();
        if (t == 0) {
            float cont = red[0] / (float)B;
            float foc = sfoc[0] / (float)B;
            float pd = (float)(B - n0), ct = (float)n0;
            float rl = 0.f;
            for (int pi = 0; pi < 6; pi++) {
                float kpd = (pd > 0.f) ? sreg[pi]     / fmaxf(pd, 1.f) : 0.f;
                float kct = (ct > 0.f) ? sreg[6 + pi] / fmaxf(ct, 1.f) : 0.f;
                rl += kpd + kct;
            }
            for (int i = 0; i < 4; i++) rl += sreg[12 + i] / (float)B;
            rl /= 10.0f;                 // R*(R-1)/2 + R = 6 + 4
            out[0] = foc + 0.5f * cont + 0.3f * rl;
        }
    }
}

// ---------------- launch ----------------
extern "C" void kernel_launch(void* const* d_in, const int* in_sizes, int n_in,
                              void* d_out, int out_size) {
    const float* logits = nullptr;
    const float* proj   = nullptr;
    const float* rp     = nullptr;
    const int*   labels = nullptr;
    for (int i = 0; i < n_in; i++) {
        switch (in_sizes[i]) {
            case B * 2:        logits = (const float*)d_in[i]; break;
            case B * D:        proj   = (const float*)d_in[i]; break;
            case 4 * B * 2:    rp     = (const float*)d_in[i]; break;
            case B:            labels = (const int*)d_in[i];   break;
        }
    }
    int nsm = 0;
    cudaDeviceGetAttribute(&nsm, cudaDevAttrMultiProcessorCount, 0);
    int grid = 2 * nsm;   // all CTAs resident (launch_bounds(256,2), 72KB smem x2 <= 228KB)
    cudaFuncSetAttribute(k_fused, cudaFuncAttributeMaxDynamicSharedMemorySize, SMEM_BYTES);
    k_fused<<<grid, 256, SMEM_BYTES>>>(logits, proj, rp, labels, (float*)d_out);
}

// round 7
// speedup vs baseline: 1.2872x; 1.2537x over previous
#include <cuda_runtime.h>
#include <cuda_bf16.h>
#include <cstdint>
#include <math.h>

#define B 4096
#define D 256
#define NT 32
#define SMEM_BYTES 73728   // 2 stages x (A 128x36w + B 128x36w), words=uint32

// ---------------- persistent scratch (no allocations allowed) ----------------
__device__ int   g_bar_cnt;            // zero-init; self-resetting
__device__ volatile int g_bar_gen;
__device__ int   g_n0;
__device__ int   g_src[B];
__device__ __align__(16) uint32_t g_Ps32[B * (D / 2)];   // bf16x2-packed normalized rows
__device__ float g_RP[NT * B];         // [col-tile q][row i]  (coalesced)
__device__ float g_L[B];
__device__ int   g_crossList[NT * NT];
__device__ int   g_ncross;
__device__ int   g_withinList[NT * NT];
__device__ int   g_nwithin;
__device__ float g_part2[NT * NT];     // dense by within-list slot
__device__ float g_part_focal[16];
__device__ float g_part_region[32 * 16];

// ---------------- helpers ----------------
__device__ __forceinline__ uint32_t smem_u32(const void* p) {
    uint32_t a;
    asm("{ .reg .u64 t; cvta.to.shared.u64 t, %1; cvt.u32.u64 %0, t; }" : "=r"(a) : "l"(p));
    return a;
}
__device__ __forceinline__ void cp16(uint32_t d, const void* s) {
    asm volatile("cp.async.cg.shared.global [%0], [%1], 16;" :: "r"(d), "l"(s));
}
__device__ __forceinline__ void cp_commit() { asm volatile("cp.async.commit_group;" ::: "memory"); }
__device__ __forceinline__ void cp_wait1()  { asm volatile("cp.async.wait_group 1;" ::: "memory"); }
__device__ __forceinline__ void cp_wait0()  { asm volatile("cp.async.wait_group 0;" ::: "memory"); }
__device__ __forceinline__ uint32_t pack_bf16x2(float lo, float hi) {
    uint32_t r;
    asm("cvt.rn.bf16x2.f32 %0, %1, %2;" : "=r"(r) : "f"(hi), "f"(lo));  // hi->upper, lo->lower
    return r;
}
// fast softplus: log(1+e^x). Typical x here is ~7.7 +- 0.6; |x|<2.1 is a many-sigma event.
__device__ __forceinline__ float softplus_f(float x) {
    float ax = fabsf(x);
    float m  = fmaxf(x, 0.0f);
    float y  = __expf(-ax);
    if (ax < 2.1f) return m + log1pf(y);    // precise fallback (cold)
    float y2 = y * y;
    return m + (y - 0.5f * y2 + 0.33333333f * y2 * y - 0.25f * y2 * y2);
}

// ---------------- global sense-reversing barrier (all CTAs resident) ----------------
__device__ __forceinline__ void gbar() {
    __syncthreads();
    if (threadIdx.x == 0) {
        __threadfence();
        int gen = g_bar_gen;
        if (atomicAdd(&g_bar_cnt, 1) == (int)gridDim.x - 1) {
            g_bar_cnt = 0;
            __threadfence();
            g_bar_gen = gen + 1;
        } else {
            while (g_bar_gen == gen) __nanosleep(64);
        }
        __threadfence();
    }
    __syncthreads();
}

// ---------------- 128x128x256 bf16 tile GEMM via mma.sync m16n8k16 ----------------
// 8 warps 4(m) x 2(n); warp tile 32x64; per-warp 2x8 m16n8k16 per k16-step; acc[mt][nt][4].
// C elem map (lane l, g=l>>2, tg=l&3): c0:(mt*16+g, nt*8+tg*2) c1:(+0,+1) c2:(+8,+0) c3:(+8,+1)
// smem rows: 64 bf16 = 32 words + pad to 36 words (bank = 4g+tg, conflict-free).
__device__ __forceinline__ void gemm_tile(char* sm, uint32_t sb, int row0, int col0,
                                          float (*acc)[8][4]) {
    int t = threadIdx.x;
    int w = t >> 5, l = t & 31;
    int wm = w & 3, wn = w >> 2;
    int g = l >> 2, tg = l & 3;
#pragma unroll
    for (int mt = 0; mt < 2; mt++)
#pragma unroll
        for (int nt = 0; nt < 8; nt++)
#pragma unroll
            for (int e = 0; e < 4; e++) acc[mt][nt][e] = 0.f;

    const char* gp = (const char*)g_Ps32;   // row stride 512B (256 bf16)

#pragma unroll
    for (int u = 0; u < 4; u++) {           // prefetch chunk 0 (K=64 -> 128B/row)
        int idx = t + 256 * u, r = idx >> 3, q = idx & 7;
        uint32_t so = (uint32_t)(r * 36 + q * 4) * 4u;
        cp16(sb + so, gp + (size_t)(row0 + r) * 512 + q * 16);
        cp16(sb + 18432u + so, gp + (size_t)(col0 + r) * 512 + q * 16);
    }
    cp_commit();

    for (int c = 0; c < 4; c++) {
        uint32_t pb = (uint32_t)(c & 1) * 36864u;
        if (c < 3) {
            uint32_t nb = (uint32_t)((c + 1) & 1) * 36864u;
            int koff = (c + 1) * 128;       // byte offset within row
#pragma unroll
            for (int u = 0; u < 4; u++) {
                int idx = t + 256 * u, r = idx >> 3, q = idx & 7;
                uint32_t so = (uint32_t)(r * 36 + q * 4) * 4u;
                cp16(sb + nb + so, gp + (size_t)(row0 + r) * 512 + koff + q * 16);
                cp16(sb + nb + 18432u + so, gp + (size_t)(col0 + r) * 512 + koff + q * 16);
            }
            cp_commit();
            cp_wait1();
        } else {
            cp_wait0();
        }
        __syncthreads();
        const uint32_t* Asm = (const uint32_t*)(sm + pb);
        const uint32_t* Bsm = (const uint32_t*)(sm + pb + 18432);
#pragma unroll
        for (int ks = 0; ks < 4; ks++) {    // 4 x k16 = K64
            int k0w = ks * 8;
            uint32_t a[2][4], b[8][2];
#pragma unroll
            for (int mt = 0; mt < 2; mt++) {
                int ar = wm * 32 + mt * 16 + g;
                a[mt][0] = Asm[ar * 36 + k0w + tg];            // row g,   k 2tg..2tg+1
                a[mt][1] = Asm[(ar + 8) * 36 + k0w + tg];      // row g+8, k lo
                a[mt][2] = Asm[ar * 36 + k0w + tg + 4];        // row g,   k 2tg+8..
                a[mt][3] = Asm[(ar + 8) * 36 + k0w + tg + 4];  // row g+8, k hi
            }
#pragma unroll
            for (int nt = 0; nt < 8; nt++) {
                int br = wn * 64 + nt * 8 + g;
                b[nt][0] = Bsm[br * 36 + k0w + tg];            // n g-col, k lo pair
                b[nt][1] = Bsm[br * 36 + k0w + tg + 4];        // k hi pair
            }
#pragma unroll
            for (int mt = 0; mt < 2; mt++)
#pragma unroll
                for (int nt = 0; nt < 8; nt++)
                    asm volatile(
                        "mma.sync.aligned.m16n8k16.row.col.f32.bf16.bf16.f32 "
                        "{%0,%1,%2,%3}, {%4,%5,%6,%7}, {%8,%9}, {%0,%1,%2,%3};"
                        : "+f"(acc[mt][nt][0]), "+f"(acc[mt][nt][1]),
                          "+f"(acc[mt][nt][2]), "+f"(acc[mt][nt][3])
                        : "r"(a[mt][0]), "r"(a[mt][1]), "r"(a[mt][2]), "r"(a[mt][3]),
                          "r"(b[nt][0]), "r"(b[nt][1]));
        }
        __syncthreads();
    }
}

// ---------------- cross tile: row/col sums of exp(sim/T) over neg pairs ----------------
__device__ void cross_tile(char* sm, int by, int bx, int n0) {
    int row0 = by * 128, col0 = bx * 128;
    float acc[2][8][4];
    gemm_tile(sm, smem_u32(sm), row0, col0, acc);

    int t = threadIdx.x;
    int w = t >> 5, l = t & 31;
    int wm = w & 3, wn = w >> 2;
    int g = l >> 2, tg = l & 3;

    float rowp[2][2] = {{0.f,0.f},{0.f,0.f}};
    float colp[8][2];
#pragma unroll
    for (int nt = 0; nt < 8; nt++) { colp[nt][0] = 0.f; colp[nt][1] = 0.f; }
#pragma unroll
    for (int mt = 0; mt < 2; mt++) {
        int r0 = row0 + wm * 32 + mt * 16 + g;
        int r1 = r0 + 8;
        bool ga = (r0 < n0), gb = (r1 < n0);
#pragma unroll
        for (int nt = 0; nt < 8; nt++) {
            int c0 = col0 + wn * 64 + nt * 8 + tg * 2;
            bool ca = (c0 < n0), cb = (c0 + 1 < n0);
            float e00 = (ga != ca) ? __expf(acc[mt][nt][0] * 10.0f) : 0.f;
            float e01 = (ga != cb) ? __expf(acc[mt][nt][1] * 10.0f) : 0.f;
            float e10 = (gb != ca) ? __expf(acc[mt][nt][2] * 10.0f) : 0.f;
            float e11 = (gb != cb) ? __expf(acc[mt][nt][3] * 10.0f) : 0.f;
            rowp[mt][0] += e00 + e01;
            rowp[mt][1] += e10 + e11;
            colp[nt][0] += e00 + e10;
            colp[nt][1] += e01 + e11;
        }
    }
#pragma unroll
    for (int mt = 0; mt < 2; mt++)
#pragma unroll
        for (int h = 0; h < 2; h++) {
            rowp[mt][h] += __shfl_xor_sync(0xffffffffu, rowp[mt][h], 1);
            rowp[mt][h] += __shfl_xor_sync(0xffffffffu, rowp[mt][h], 2);
        }
#pragma unroll
    for (int nt = 0; nt < 8; nt++)
#pragma unroll
        for (int h = 0; h < 2; h++) {
            colp[nt][h] += __shfl_xor_sync(0xffffffffu, colp[nt][h], 4);
            colp[nt][h] += __shfl_xor_sync(0xffffffffu, colp[nt][h], 8);
            colp[nt][h] += __shfl_xor_sync(0xffffffffu, colp[nt][h], 16);
        }
    float* rowred = (float*)sm;            // [2][128]
    float* colred = (float*)(sm + 1024);   // [4][128]
    if (tg == 0) {
#pragma unroll
        for (int mt = 0; mt < 2; mt++) {
            rowred[wn * 128 + wm * 32 + mt * 16 + g]     = rowp[mt][0];
            rowred[wn * 128 + wm * 32 + mt * 16 + g + 8] = rowp[mt][1];
        }
    }
    if (l < 4) {
#pragma unroll
        for (int nt = 0; nt < 8; nt++)
#pragma unroll
            for (int h = 0; h < 2; h++)
                colred[wm * 128 + wn * 64 + nt * 8 + l * 2 + h] = colp[nt][h];
    }
    __syncthreads();
    if (t < 128) {
        float rs = rowred[t] + rowred[128 + t];
        float cs = colred[t] + colred[128 + t] + colred[256 + t] + colred[384 + t];
        int r = row0 + t, c = col0 + t;
        if (r < n0)  g_RP[bx * B + r] = rs;   // coalesced column-tile-major
        if (c >= n0) g_RP[by * B + c] = cs;
    }
    __syncthreads();
}

// ---------------- within epilogue: sum softplus(L - sim/T) over pos pairs ----------------
__device__ void within_epilogue(char* sm, int by, int bx, int n0, int slot,
                                float (*acc)[8][4]) {
    int row0 = by * 128, col0 = bx * 128;
    int t = threadIdx.x;
    int w = t >> 5, l = t & 31;
    int wm = w & 3, wn = w >> 2;
    int g = l >> 2, tg = l & 3;
    bool offd = (bx > by);

    float Lr[2][2], Lc[8][2];
#pragma unroll
    for (int mt = 0; mt < 2; mt++) {
        int r0 = row0 + wm * 32 + mt * 16 + g;
        Lr[mt][0] = g_L[r0];
        Lr[mt][1] = g_L[r0 + 8];
    }
#pragma unroll
    for (int nt = 0; nt < 8; nt++) {
        int c0 = col0 + wn * 64 + nt * 8 + tg * 2;
        Lc[nt][0] = g_L[c0];
        Lc[nt][1] = g_L[c0 + 1];
    }
    float local = 0.f;
#pragma unroll
    for (int mt = 0; mt < 2; mt++) {
        int r0 = row0 + wm * 32 + mt * 16 + g;
#pragma unroll
        for (int nt = 0; nt < 8; nt++) {
            int c0 = col0 + wn * 64 + nt * 8 + tg * 2;
#pragma unroll
            for (int e = 0; e < 4; e++) {
                int r = r0 + (e >> 1) * 8;
                int c = c0 + (e & 1);
                if (((r < n0) == (c < n0)) && (r != c)) {
                    float s10 = acc[mt][nt][e] * 10.0f;
                    local += softplus_f(Lr[mt][e >> 1] - s10);
                    if (offd) local += softplus_f(Lc[nt][e & 1] - s10);
                }
            }
        }
    }
    float* red = (float*)sm;
    red[t] = local;
    __syncthreads();
    for (int off = 128; off > 0; off >>= 1) { if (t < off) red[t] += red[t + off]; __syncthreads(); }
    if (t == 0) g_part2[slot] = red[0];
    __syncthreads();
}

// ---------------- the single persistent kernel ----------------
__global__ void __launch_bounds__(256, 2) k_fused(
    const float* __restrict__ logits, const float* __restrict__ proj,
    const float* __restrict__ rp, const int* __restrict__ labels,
    float* __restrict__ out)
{
    extern __shared__ char sm[];
    const int grid = gridDim.x;
    const int cta = blockIdx.x;
    const int t = threadIdx.x;

    // ===== phase 0: CTA0 scan + tile lists; CTAs 1-16 focal; 17-48 region =====
    if (cta == 0) {
        int* sd = (int*)sm;
        int base = t * 16, cnt = 0, zm = 0;
#pragma unroll
        for (int u = 0; u < 16; u++) {
            int lz = (labels[base + u] == 0) ? 1 : 0;
            zm |= lz << u; cnt += lz;
        }
        sd[t] = cnt;
        __syncthreads();
        for (int off = 1; off < 256; off <<= 1) {
            int v = (t >= off) ? sd[t - off] : 0;
            __syncthreads();
            sd[t] += v;
            __syncthreads();
        }
        int n0 = sd[255];
        int zb = sd[t] - cnt;
#pragma unroll
        for (int u = 0; u < 16; u++) {
            int i = base + u, dest;
            if ((zm >> u) & 1) { dest = zb; zb++; }
            else               { dest = n0 + (i - zb); }
            g_src[dest] = i;
        }
        if (t == 0) g_n0 = n0;
        __syncthreads();
        // cross list: active iff row0 < n0 && col0+127 >= n0
        {
            int fl[4], c2 = 0;
#pragma unroll
            for (int u = 0; u < 4; u++) {
                int idx = t * 4 + u, by = idx >> 5, bx = idx & 31;
                fl[u] = (by * 128 < n0 && bx * 128 + 127 >= n0) ? 1 : 0;
                c2 += fl[u];
            }
            sd[t] = c2;
            __syncthreads();
            for (int off = 1; off < 256; off <<= 1) {
                int v = (t >= off) ? sd[t - off] : 0;
                __syncthreads();
                sd[t] += v;
                __syncthreads();
            }
            int pos = sd[t] - c2;
#pragma unroll
            for (int u = 0; u < 4; u++)
                if (fl[u]) g_crossList[pos++] = t * 4 + u;
            if (t == 255) g_ncross = sd[255];
            __syncthreads();
        }
        // within list: active iff bx>=by && !(row0+127 < n0 && col0 >= n0)
        {
            int fl[4], c2 = 0;
#pragma unroll
            for (int u = 0; u < 4; u++) {
                int idx = t * 4 + u, by = idx >> 5, bx = idx & 31;
                fl[u] = (bx >= by && !((by * 128 + 127 < n0) && (bx * 128 >= n0))) ? 1 : 0;
                c2 += fl[u];
            }
            sd[t] = c2;
            __syncthreads();
            for (int off = 1; off < 256; off <<= 1) {
                int v = (t >= off) ? sd[t - off] : 0;
                __syncthreads();
                sd[t] += v;
                __syncthreads();
            }
            int pos = sd[t] - c2;
#pragma unroll
            for (int u = 0; u < 4; u++)
                if (fl[u]) g_withinList[pos++] = t * 4 + u;
            if (t == 255) g_nwithin = sd[255];
            __syncthreads();
        }
    } else if (cta <= 16) {
        // focal: 256 elems per CTA
        float* red = (float*)sm;
        int i = (cta - 1) * 256 + t;
        float z0 = logits[2 * i] / 1.5f;
        float z1 = logits[2 * i + 1] / 1.5f;
        float m = fmaxf(z0, z1);
        float lse = m + logf(expf(z0 - m) + expf(z1 - m));
        float ce = lse - (labels[i] ? z1 : z0);
        float pt = expf(-ce);
        float om = 1.0f - pt;
        red[t] = om * om * ce;
        __syncthreads();
        for (int off = 128; off > 0; off >>= 1) { if (t < off) red[t] += red[t + off]; __syncthreads(); }
        if (t == 0) g_part_focal[cta - 1] = red[0];
    } else if (cta <= 48) {
        // region: 128 elems per CTA (threads 0-127 active)
        float (*red)[128] = (float (*)[128])sm;
        int rb = cta - 17;
        float accv[16];
#pragma unroll
        for (int k = 0; k < 16; k++) accv[k] = 0.f;
        if (t < 128) {
            int b = rb * 128 + t;
            int lab = labels[b];
            float p[4][2], lp[4][2], lpe[4][2], ent[4];
#pragma unroll
            for (int i = 0; i < 4; i++) {
                float x0 = rp[(i * B + b) * 2 + 0];
                float x1 = rp[(i * B + b) * 2 + 1];
                float m = fmaxf(x0, x1);
                float lse = m + logf(expf(x0 - m) + expf(x1 - m));
                lp[i][0] = x0 - lse; lp[i][1] = x1 - lse;
                p[i][0] = expf(lp[i][0]); p[i][1] = expf(lp[i][1]);
                lpe[i][0] = logf(p[i][0] + 1e-10f);
                lpe[i][1] = logf(p[i][1] + 1e-10f);
                ent[i] = p[i][0] * lp[i][0] + p[i][1] * lp[i][1];
                accv[12 + i] += -(lab ? lp[i][1] : lp[i][0]);
            }
            int pi = 0;
#pragma unroll
            for (int i = 0; i < 4; i++)
#pragma unroll
                for (int j = i + 1; j < 4; j++, pi++) {
                    float kl = ent[j] - (p[j][0] * lpe[i][0] + p[j][1] * lpe[i][1]);
                    if (lab) accv[pi] += kl; else accv[6 + pi] += kl;
                }
#pragma unroll
            for (int k = 0; k < 16; k++) red[k][t] = accv[k];
        }
        __syncthreads();
        for (int off = 64; off > 0; off >>= 1) {
            if (t < off) {
#pragma unroll
                for (int k = 0; k < 16; k++) red[k][t] += red[k][t + off];
            }
            __syncthreads();
        }
        if (t < 16) g_part_region[rb * 16 + t] = red[t][0];
    }
    gbar();

    // ===== phase 1: gather + L2-normalize + bf16-pack =====
    {
        int gw = (cta * 256 + t) >> 5;
        int lane = t & 31;
        int nw = grid * 8;
        for (int row = gw; row < B; row += nw) {
            int src = g_src[row];
            const float4* rrow = (const float4*)(proj + (size_t)src * D);
            float4 p0 = rrow[lane * 2];
            float4 p1 = rrow[lane * 2 + 1];
            float ss = p0.x*p0.x + p0.y*p0.y + p0.z*p0.z + p0.w*p0.w
                     + p1.x*p1.x + p1.y*p1.y + p1.z*p1.z + p1.w*p1.w;
#pragma unroll
            for (int o = 16; o > 0; o >>= 1) ss += __shfl_xor_sync(0xffffffffu, ss, o);
            float inv = 1.0f / fmaxf(sqrtf(ss), 1e-12f);
            uint32_t* outp = g_Ps32 + (size_t)row * 128 + lane * 4;
            outp[0] = pack_bf16x2(p0.x * inv, p0.y * inv);
            outp[1] = pack_bf16x2(p0.z * inv, p0.w * inv);
            outp[2] = pack_bf16x2(p1.x * inv, p1.y * inv);
            outp[3] = pack_bf16x2(p1.z * inv, p1.w * inv);
        }
    }
    gbar();

    // ===== phase 2: ALL tile GEMMs (cross full; within GEMM held in regs) =====
    int n0 = g_n0;
    float accW[2][8][4];
    int heldSlot = -1, heldTile = 0;
    int nDefer = 0;
    int deferList[4];
    {
        int nc = g_ncross, nwv = g_nwithin, tot = nc + nwv;
        for (int wk = cta; wk < tot; wk += grid) {
            if (wk < nc) {
                int tile = g_crossList[wk];
                cross_tile(sm, tile >> 5, tile & 31, n0);
            } else {
                int slot = wk - nc;
                if (heldSlot < 0) {
                    heldSlot = slot;
                    heldTile = g_withinList[slot];
                    gemm_tile(sm, smem_u32(sm), (heldTile >> 5) * 128,
                              (heldTile & 31) * 128, accW);
                } else if (nDefer < 4) {
                    deferList[nDefer++] = slot;   // rare overflow: recompute after L
                }
            }
        }
    }
    gbar();

    // ===== phase 3: L[i] = log(sum of partials), coalesced =====
    {
        int i = cta * 256 + t;
        if (i < B) {
            int lo, hi;
            if (i < n0) { lo = n0 >> 7; hi = NT - 1; }
            else        { lo = 0; hi = (n0 - 1) >> 7; }
            float s = 0.f;
            for (int q = lo; q <= hi; q++) s += g_RP[q * B + i];
            g_L[i] = logf(s);
        }
    }
    gbar();

    // ===== phase 4: within epilogues (held acc) + deferred recompute =====
    if (heldSlot >= 0)
        within_epilogue(sm, heldTile >> 5, heldTile & 31, n0, heldSlot, accW);
    for (int d2 = 0; d2 < nDefer; d2++) {
        int slot = deferList[d2];
        int tile = g_withinList[slot];
        float accD[2][8][4];
        gemm_tile(sm, smem_u32(sm), (tile >> 5) * 128, (tile & 31) * 128, accD);
        within_epilogue(sm, tile >> 5, tile & 31, n0, slot, accD);
    }
    gbar();

    // ===== phase 5: final combine (CTA 0) =====
    if (cta == 0) {
        float* red = (float*)sm;
        float* sreg = (float*)(sm + 1024);
        float* sfoc = (float*)(sm + 1024 + 64);
        int nwv = g_nwithin;
        float s = 0.f;
        for (int i = t; i < nwv; i += 256) s += g_part2[i];
        red[t] = s;
        __syncthreads();
        for (int off = 128; off > 0; off >>= 1) { if (t < off) red[t] += red[t + off]; __syncthreads(); }
        if (t < 16) {
            float a = 0.f;
            for (int blk = 0; blk < 32; blk++) a += g_part_region[blk * 16 + t];
            sreg[t] = a;
        }
        if (t == 16) {
            float f = 0.f;
            for (int i = 0; i < 16; i++) f += g_part_focal[i];
            sfoc[0] = f;
        }
        __syncthreads();
        if (t == 0) {
            float cont = red[0] / (float)B;
            float foc = sfoc[0] / (float)B;
            float pd = (float)(B - n0), ct = (float)n0;
            float rl = 0.f;
            for (int pi = 0; pi < 6; pi++) {
                float kpd = (pd > 0.f) ? sreg[pi]     / fmaxf(pd, 1.f) : 0.f;
                float kct = (ct > 0.f) ? sreg[6 + pi] / fmaxf(ct, 1.f) : 0.f;
                rl += kpd + kct;
            }
            for (int i = 0; i < 4; i++) rl += sreg[12 + i] / (float)B;
            rl /= 10.0f;                 // R*(R-1)/2 + R = 6 + 4
            out[0] = foc + 0.5f * cont + 0.3f * rl;
        }
    }
}

// ---------------- launch ----------------
extern "C" void kernel_launch(void* const* d_in, const int* in_sizes, int n_in,
                              void* d_out, int out_size) {
    const float* logits = nullptr;
    const float* proj   = nullptr;
    const float* rp     = nullptr;
    const int*   labels = nullptr;
    for (int i = 0; i < n_in; i++) {
        switch (in_sizes[i]) {
            case B * 2:        logits = (const float*)d_in[i]; break;
            case B * D:        proj   = (const float*)d_in[i]; break;
            case 4 * B * 2:    rp     = (const float*)d_in[i]; break;
            case B:            labels = (const int*)d_in[i];   break;
        }
    }
    int nsm = 0;
    cudaDeviceGetAttribute(&nsm, cudaDevAttrMultiProcessorCount, 0);
    int grid = 2 * nsm;   // all CTAs resident (launch_bounds(256,2), 72KB smem x2 <= 228KB)
    cudaFuncSetAttribute(k_fused, cudaFuncAttributeMaxDynamicSharedMemorySize, SMEM_BYTES);
    k_fused<<<grid, 256, SMEM_BYTES>>>(logits, proj, rp, labels, (float*)d_out);
}